// round 1
// baseline (speedup 1.0000x reference)
#include <cuda_runtime.h>
#include <cuda_bf16.h>

#define BATCH 8192
#define SEQ   40
#define HID   256
#define VOCAB 128
#define G4    (4 * HID)  // 1024

// Scratch state (no cudaMalloc allowed): h ping-pong + c
__device__ float g_h[2][BATCH * HID];
__device__ float g_c[BATCH * HID];

__device__ __forceinline__ float sigmoidf_(float x) {
    return 1.0f / (1.0f + __expf(-x));
}

__global__ void init_state_kernel() {
    int i = blockIdx.x * blockDim.x + threadIdx.x;
    if (i < BATCH * HID) {
        g_h[0][i] = 0.0f;
        g_c[i]    = 0.0f;
    }
}

// ---------------------------------------------------------------------------
// One LSTM step, fused: z = gather(Wx, idx) + h_prev @ Wh + b ; gates ; c,h.
// Tile: BM=64 batch rows x BJ=64 hidden units, all 4 gates (cols j, j+256,
// j+512, j+768 of Wh). K=256. 256 threads, 4x4 microtile x 4 gates = 64 acc.
// ---------------------------------------------------------------------------
#define BM 64
#define BJ 64
#define KC 16

__global__ __launch_bounds__(256) void lstm_step_kernel(
    int t,
    const int*   __restrict__ inputs,   // [BATCH, SEQ]
    const float* __restrict__ Wx,       // [128, 1024]
    const float* __restrict__ Wh,       // [256, 1024]
    const float* __restrict__ bias)     // [1024]
{
    const float* __restrict__ hin  = g_h[t & 1];
    float*       __restrict__ hout = g_h[(t + 1) & 1];

    const int b0  = blockIdx.x * BM;
    const int j0  = blockIdx.y * BJ;
    const int tid = threadIdx.x;
    const int tx  = tid & 15;   // hidden micro (4 cols)
    const int ty  = tid >> 4;   // batch micro (4 rows)

    __shared__ __align__(16) float As[KC][BM];        // h chunk, transposed
    __shared__ __align__(16) float Bs[4][KC][BJ];     // Wh chunk, 4 gates
    __shared__ int idx_s[BM];

    if (tid < BM) idx_s[tid] = inputs[(b0 + tid) * SEQ + t];

    float acc[4][4][4];  // [gate][bi][ji]
#pragma unroll
    for (int g = 0; g < 4; g++)
#pragma unroll
        for (int i = 0; i < 4; i++)
#pragma unroll
            for (int j = 0; j < 4; j++) acc[g][i][j] = 0.0f;

    const int arow = tid >> 2, aq = tid & 3;   // A: one float4 per thread
    const int bkk = tid >> 4, bjq = tid & 15;  // B: one float4 per gate per thread

    for (int k0 = 0; k0 < HID; k0 += KC) {
        __syncthreads();  // previous chunk's reads done (also covers idx_s)

        float4 av = *(const float4*)&hin[(b0 + arow) * HID + k0 + aq * 4];
        As[aq * 4 + 0][arow] = av.x;
        As[aq * 4 + 1][arow] = av.y;
        As[aq * 4 + 2][arow] = av.z;
        As[aq * 4 + 3][arow] = av.w;
#pragma unroll
        for (int g = 0; g < 4; g++) {
            float4 bv = *(const float4*)&Wh[(k0 + bkk) * G4 + g * HID + j0 + bjq * 4];
            *(float4*)&Bs[g][bkk][bjq * 4] = bv;
        }
        __syncthreads();

#pragma unroll
        for (int kk = 0; kk < KC; kk++) {
            float4 af = *(const float4*)&As[kk][ty * 4];
            float a[4] = {af.x, af.y, af.z, af.w};
#pragma unroll
            for (int g = 0; g < 4; g++) {
                float4 bf = *(const float4*)&Bs[g][kk][tx * 4];
                float bb[4] = {bf.x, bf.y, bf.z, bf.w};
#pragma unroll
                for (int i = 0; i < 4; i++)
#pragma unroll
                    for (int j = 0; j < 4; j++)
                        acc[g][i][j] += a[i] * bb[j];
            }
        }
    }

    // Bias (same for all batch rows in tile) — hoist once.
    float4 bb4[4];
#pragma unroll
    for (int g = 0; g < 4; g++)
        bb4[g] = *(const float4*)&bias[g * HID + j0 + tx * 4];

    // Epilogue: + one-hot gather + bias, gates, state update.
#pragma unroll
    for (int i = 0; i < 4; i++) {
        const int b    = b0 + ty * 4 + i;
        const int crow = idx_s[ty * 4 + i];

#pragma unroll
        for (int g = 0; g < 4; g++) {
            float4 wx = *(const float4*)&Wx[crow * G4 + g * HID + j0 + tx * 4];
            float4 bb = bb4[g];
            acc[g][i][0] += wx.x + bb.x;
            acc[g][i][1] += wx.y + bb.y;
            acc[g][i][2] += wx.z + bb.z;
            acc[g][i][3] += wx.w + bb.w;
        }

        float4 cold = *(const float4*)&g_c[b * HID + j0 + tx * 4];
        float co[4] = {cold.x, cold.y, cold.z, cold.w};
        float cn[4], hn[4];
#pragma unroll
        for (int j = 0; j < 4; j++) {
            float ig = sigmoidf_(acc[0][i][j]);   // keras order: i, f, g, o
            float fg = sigmoidf_(acc[1][i][j]);
            float gg = tanhf(acc[2][i][j]);
            float og = sigmoidf_(acc[3][i][j]);
            float cc = fg * co[j] + ig * gg;
            cn[j] = cc;
            hn[j] = og * tanhf(cc);
        }
        *(float4*)&g_c[b * HID + j0 + tx * 4] = make_float4(cn[0], cn[1], cn[2], cn[3]);
        *(float4*)&hout[b * HID + j0 + tx * 4] = make_float4(hn[0], hn[1], hn[2], hn[3]);
    }
}

// ---------------------------------------------------------------------------
// Dense + softmax: logits = h @ Wd + bd ; softmax over 128 vocab.
// 8 batch rows per block, one thread per vocab column.
// ---------------------------------------------------------------------------
#define DROWS 8

__global__ __launch_bounds__(128) void dense_softmax_kernel(
    const float* __restrict__ Wd,   // [256, 128]
    const float* __restrict__ bd,   // [128]
    float*       __restrict__ out)  // [BATCH, 128]
{
    const float* __restrict__ h = g_h[SEQ & 1];  // SEQ=40 even -> g_h[0]
    const int b0  = blockIdx.x * DROWS;
    const int tid = threadIdx.x;

    __shared__ float hs[DROWS][HID];
    __shared__ float ls[DROWS][VOCAB];

#pragma unroll
    for (int s = 0; s < DROWS * HID / 128; s++) {
        int e = tid + s * 128;
        hs[e >> 8][e & 255] = h[b0 * HID + e];  // h rows contiguous
    }
    __syncthreads();

    float acc[DROWS];
    float bv = bd[tid];
#pragma unroll
    for (int r = 0; r < DROWS; r++) acc[r] = bv;

#pragma unroll 8
    for (int k = 0; k < HID; k++) {
        float w = Wd[k * VOCAB + tid];
#pragma unroll
        for (int r = 0; r < DROWS; r++) acc[r] += hs[r][k] * w;
    }

#pragma unroll
    for (int r = 0; r < DROWS; r++) ls[r][tid] = acc[r];
    __syncthreads();

    // Softmax: 4 warps x 2 rows each, 4 cols/lane.
    const int w = tid >> 5, lane = tid & 31;
#pragma unroll
    for (int rr = 0; rr < 2; rr++) {
        int r = w * 2 + rr;
        float v[4];
        float m = -1e30f;
#pragma unroll
        for (int q = 0; q < 4; q++) {
            v[q] = ls[r][lane + q * 32];
            m = fmaxf(m, v[q]);
        }
#pragma unroll
        for (int o = 16; o > 0; o >>= 1) m = fmaxf(m, __shfl_xor_sync(0xffffffffu, m, o));
        float s = 0.0f;
#pragma unroll
        for (int q = 0; q < 4; q++) {
            v[q] = __expf(v[q] - m);
            s += v[q];
        }
#pragma unroll
        for (int o = 16; o > 0; o >>= 1) s += __shfl_xor_sync(0xffffffffu, s, o);
        float inv = 1.0f / s;
#pragma unroll
        for (int q = 0; q < 4; q++)
            out[(b0 + r) * VOCAB + lane + q * 32] = v[q] * inv;
    }
}

extern "C" void kernel_launch(void* const* d_in, const int* in_sizes, int n_in,
                              void* d_out, int out_size) {
    const int*   inputs = (const int*)d_in[0];
    const float* Wx     = (const float*)d_in[1];
    const float* Wh     = (const float*)d_in[2];
    const float* b      = (const float*)d_in[3];
    const float* Wd     = (const float*)d_in[4];
    const float* bd     = (const float*)d_in[5];
    float*       out    = (float*)d_out;

    init_state_kernel<<<(BATCH * HID + 255) / 256, 256>>>();

    dim3 grid(BATCH / BM, HID / BJ);  // 128 x 4
    for (int t = 0; t < SEQ; t++)
        lstm_step_kernel<<<grid, 256>>>(t, inputs, Wx, Wh, b);

    dense_softmax_kernel<<<BATCH / DROWS, 128>>>(Wd, bd, out);
}

// round 3
// speedup vs baseline: 1.9907x; 1.9907x over previous
#include <cuda_runtime.h>
#include <cuda_fp16.h>
#include <cstdint>

#define BATCH 8192
#define SEQ   40
#define HID   256
#define VOCAB 128

// ===========================================================================
// Global scratch (no cudaMalloc allowed)
// ===========================================================================
__device__ __half g_hh[2][BATCH * HID];   // h hi plane, ping-pong
__device__ __half g_hl[2][BATCH * HID];   // h lo plane
__device__ float  g_c[BATCH * HID];       // cell state
// Wh split + transposed: [jt(8)][split(2)][kc(4)][n(128)][k(64)] fp16, linear.
// n = gate*32 + jj (jj = j within 32-col block), k = kc*64 + kk.
__device__ __half g_Bp[8][2][4][128 * 64];

__device__ __forceinline__ uint32_t smem_to_u32(const void* p) {
    uint32_t a;
    asm("{ .reg .u64 tmp; cvta.to.shared.u64 tmp, %1; cvt.u32.u64 %0, tmp; }"
        : "=r"(a) : "l"(p));
    return a;
}

#define LDSM_X4(r0, r1, r2, r3, addr) \
    asm volatile("ldmatrix.sync.aligned.m8n8.x4.shared.b16 {%0,%1,%2,%3}, [%4];" \
        : "=r"(r0), "=r"(r1), "=r"(r2), "=r"(r3) : "r"(addr))

#define MMA16816(d, a, b) \
    asm volatile("mma.sync.aligned.m16n8k16.row.col.f32.f16.f16.f32 " \
        "{%0,%1,%2,%3}, {%4,%5,%6,%7}, {%8,%9}, {%0,%1,%2,%3};" \
        : "+f"((d)[0]), "+f"((d)[1]), "+f"((d)[2]), "+f"((d)[3]) \
        : "r"((a)[0]), "r"((a)[1]), "r"((a)[2]), "r"((a)[3]), \
          "r"((b)[0]), "r"((b)[1]))

__device__ __forceinline__ float sigf(float x) {
    return 1.0f / (1.0f + __expf(-x));
}
__device__ __forceinline__ float tanh_(float x) {
    float ax = fabsf(x);
    float e  = __expf(-2.0f * ax);
    float r  = (1.0f - e) / (1.0f + e);
    return copysignf(r, x);
}

// ===========================================================================
// Prep: split Wh into fp16 hi/lo, transpose into per-(jt,kc) B tiles
// ===========================================================================
__global__ void prep_wh_kernel(const float* __restrict__ Wh) {
    int e = blockIdx.x * blockDim.x + threadIdx.x;  // 0 .. 262143
    int k = e >> 10, col = e & 1023;
    float v = Wh[e];
    __half hi = __float2half(v);
    __half lo = __float2half(v - __half2float(hi));
    int gate = col >> 8, j = col & 255;
    int jt = j >> 5, jj = j & 31;
    int n = gate * 32 + jj;
    int kc = k >> 6, kk = k & 63;
    g_Bp[jt][0][kc][n * 64 + kk] = hi;
    g_Bp[jt][1][kc][n * 64 + kk] = lo;
}

__global__ void init_state_kernel() {
    int i = blockIdx.x * blockDim.x + threadIdx.x;
    if (i < BATCH * HID) {
        g_hh[0][i] = __float2half(0.0f);
        g_hl[0][i] = __float2half(0.0f);
        g_c[i]     = 0.0f;
    }
}

// ===========================================================================
// LSTM step. CTA: 128 batch x (4 gates x 32 j). 256 threads = 8 warps,
// warp grid 2(M) x 4(jw); warp tile M=64 x (4 gates x 8 j).
// K=256 in 4 chunks of 64. SMEM tiles SW128-swizzled for ldmatrix.
// SMEM: A_hi[16KB] A_lo[16KB] B_hi[16KB] B_lo[16KB] = 64KB.
// ===========================================================================
#define SMEM_TOTAL 65536

__global__ __launch_bounds__(256, 2) void lstm_step_kernel(
    int t,
    const int*   __restrict__ inputs,   // [BATCH, SEQ]
    const float* __restrict__ Wx,       // [128, 1024]
    const float* __restrict__ bias)     // [1024]
{
    extern __shared__ __align__(128) unsigned char smem[];
    const uint32_t sbase = smem_to_u32(smem);
    const int tid  = threadIdx.x;
    const int lane = tid & 31, wid = tid >> 5;
    const int mw = wid >> 2;          // 0..1  (64-row M slab)
    const int jw = wid & 3;           // 0..3  (8-col j slab)
    const int b0 = blockIdx.x * 128;
    const int jt = blockIdx.y;        // 0..7
    const int j0 = jt * 32;

    const __half* __restrict__ hh_in = g_hh[t & 1];
    const __half* __restrict__ hl_in = g_hl[t & 1];
    __half* __restrict__ hh_out = g_hh[(t + 1) & 1];
    __half* __restrict__ hl_out = g_hl[(t + 1) & 1];

    float acc[4][4][4];
#pragma unroll
    for (int mt = 0; mt < 4; mt++)
#pragma unroll
        for (int g = 0; g < 4; g++)
#pragma unroll
            for (int e = 0; e < 4; e++) acc[mt][g][e] = 0.0f;

    // ldmatrix per-lane geometry (constant across chunks)
    const int p  = lane >> 3;        // quadrant 0..3
    const int l7 = lane & 7;
    const int rA_base = mw * 64 + (p & 1) * 8 + l7;   // + mt*16
    const int cA_base = (p >> 1);                      // + ks*2
    const int gB = p >> 1;                             // gate within pair
    const int cB_base = (p & 1);                       // + ks*2
    const int nB_base = jw * 8 + l7;                   // + g*32

#pragma unroll 1
    for (int kc = 0; kc < 4; kc++) {
        __syncthreads();
        // ---- copy A (h hi/lo) and B (Wh hi/lo) chunk into swizzled SMEM
#pragma unroll
        for (int s = 0; s < 2; s++) {
            const uint4* asrc = (const uint4*)((s ? hl_in : hh_in)
                                + (size_t)b0 * HID + kc * 64);
            const uint4* bsrc = (const uint4*)&g_Bp[jt][s][kc][0];
            unsigned char* adst = smem + s * 16384;
            unsigned char* bdst = smem + 32768 + s * 16384;
#pragma unroll
            for (int i = 0; i < 4; i++) {
                int q   = tid + i * 256;       // 0..1023
                int row = q >> 3, c = q & 7;
                uint32_t doff = row * 128 + ((c ^ (row & 7)) << 4);
                *(uint4*)(adst + doff) = asrc[row * 32 + c];   // h row stride 256h
                *(uint4*)(bdst + doff) = bsrc[row * 8 + c];
            }
        }
        __syncthreads();

#pragma unroll
        for (int ks = 0; ks < 4; ks++) {
            uint32_t ah[4][4], al[4][4], bh[4][2], bl[4][2];
            const int cA = cA_base + ks * 2;
            const int cBv = cB_base + ks * 2;
#pragma unroll
            for (int mt = 0; mt < 4; mt++) {
                int row = rA_base + mt * 16;
                uint32_t off = row * 128 + ((cA ^ (row & 7)) << 4);
                LDSM_X4(ah[mt][0], ah[mt][1], ah[mt][2], ah[mt][3], sbase + off);
                LDSM_X4(al[mt][0], al[mt][1], al[mt][2], al[mt][3],
                        sbase + 16384 + off);
            }
#pragma unroll
            for (int gp = 0; gp < 2; gp++) {
                int rowB = (gp * 2 + gB) * 32 + nB_base;
                uint32_t off = rowB * 128 + ((cBv ^ (rowB & 7)) << 4);
                LDSM_X4(bh[gp * 2][0], bh[gp * 2][1],
                        bh[gp * 2 + 1][0], bh[gp * 2 + 1][1],
                        sbase + 32768 + off);
                LDSM_X4(bl[gp * 2][0], bl[gp * 2][1],
                        bl[gp * 2 + 1][0], bl[gp * 2 + 1][1],
                        sbase + 49152 + off);
            }
#pragma unroll
            for (int mt = 0; mt < 4; mt++)
#pragma unroll
                for (int g = 0; g < 4; g++) {
                    MMA16816(acc[mt][g], ah[mt], bh[g]);
                    MMA16816(acc[mt][g], ah[mt], bl[g]);
                    MMA16816(acc[mt][g], al[mt], bh[g]);
                }
        }
    }

    // ---- Epilogue: z = acc + Wx[char] + bias -> gates -> c, h(hi/lo)
    const int gq = lane >> 2, t4 = lane & 3;
    const int jcol = j0 + jw * 8 + t4 * 2;     // absolute hidden j (even)

    float2 bias2[4];
#pragma unroll
    for (int g = 0; g < 4; g++)
        bias2[g] = *(const float2*)&bias[g * 256 + jcol];

#pragma unroll
    for (int mt = 0; mt < 4; mt++) {
#pragma unroll
        for (int rr = 0; rr < 2; rr++) {
            const int b  = b0 + mw * 64 + mt * 16 + gq + rr * 8;
            const int ch = inputs[b * SEQ + t];
            const float* wrow = Wx + (size_t)ch * 1024;
            float2 wx2[4];
#pragma unroll
            for (int g = 0; g < 4; g++)
                wx2[g] = *(const float2*)&wrow[g * 256 + jcol];
            float2 c2 = *(const float2*)&g_c[(size_t)b * HID + jcol];

            float cn[2], hn[2];
#pragma unroll
            for (int e = 0; e < 2; e++) {
                float zi = acc[mt][0][rr * 2 + e] + (e ? wx2[0].y : wx2[0].x)
                         + (e ? bias2[0].y : bias2[0].x);
                float zf = acc[mt][1][rr * 2 + e] + (e ? wx2[1].y : wx2[1].x)
                         + (e ? bias2[1].y : bias2[1].x);
                float zg = acc[mt][2][rr * 2 + e] + (e ? wx2[2].y : wx2[2].x)
                         + (e ? bias2[2].y : bias2[2].x);
                float zo = acc[mt][3][rr * 2 + e] + (e ? wx2[3].y : wx2[3].x)
                         + (e ? bias2[3].y : bias2[3].x);
                float ig = sigf(zi), fg = sigf(zf);
                float gg = tanh_(zg), og = sigf(zo);
                float cold = e ? c2.y : c2.x;
                float cc = fg * cold + ig * gg;
                cn[e] = cc;
                hn[e] = og * tanh_(cc);
            }
            *(float2*)&g_c[(size_t)b * HID + jcol] = make_float2(cn[0], cn[1]);

            __half h0 = __float2half(hn[0]), h1 = __float2half(hn[1]);
            __half l0 = __float2half(hn[0] - __half2float(h0));
            __half l1 = __float2half(hn[1] - __half2float(h1));
            *(__half2*)&hh_out[(size_t)b * HID + jcol] = __halves2half2(h0, h1);
            *(__half2*)&hl_out[(size_t)b * HID + jcol] = __halves2half2(l0, l1);
        }
    }
}

// ===========================================================================
// Dense + softmax (h = hh + hl reconstructed in f32)
// ===========================================================================
#define DROWS 8

__global__ __launch_bounds__(128) void dense_softmax_kernel(
    const float* __restrict__ Wd,   // [256, 128]
    const float* __restrict__ bd,   // [128]
    float*       __restrict__ out)  // [BATCH, 128]
{
    const __half* __restrict__ hh = g_hh[SEQ & 1];  // SEQ=40 even -> buffer 0
    const __half* __restrict__ hl = g_hl[SEQ & 1];
    const int b0  = blockIdx.x * DROWS;
    const int tid = threadIdx.x;

    __shared__ float hs[DROWS][HID];
    __shared__ float ls[DROWS][VOCAB];

#pragma unroll
    for (int s = 0; s < DROWS * HID / 128; s++) {
        int e = tid + s * 128;
        size_t ge = (size_t)b0 * HID + e;
        hs[e >> 8][e & 255] = __half2float(hh[ge]) + __half2float(hl[ge]);
    }
    __syncthreads();

    float acc[DROWS];
    float bv = bd[tid];
#pragma unroll
    for (int r = 0; r < DROWS; r++) acc[r] = bv;

#pragma unroll 8
    for (int k = 0; k < HID; k++) {
        float w = Wd[k * VOCAB + tid];
#pragma unroll
        for (int r = 0; r < DROWS; r++) acc[r] += hs[r][k] * w;
    }

#pragma unroll
    for (int r = 0; r < DROWS; r++) ls[r][tid] = acc[r];
    __syncthreads();

    const int w = tid >> 5, lane = tid & 31;
#pragma unroll
    for (int rr = 0; rr < 2; rr++) {
        int r = w * 2 + rr;
        float v[4];
        float m = -1e30f;
#pragma unroll
        for (int q = 0; q < 4; q++) {
            v[q] = ls[r][lane + q * 32];
            m = fmaxf(m, v[q]);
        }
#pragma unroll
        for (int o = 16; o > 0; o >>= 1) m = fmaxf(m, __shfl_xor_sync(0xffffffffu, m, o));
        float s = 0.0f;
#pragma unroll
        for (int q = 0; q < 4; q++) {
            v[q] = __expf(v[q] - m);
            s += v[q];
        }
#pragma unroll
        for (int o = 16; o > 0; o >>= 1) s += __shfl_xor_sync(0xffffffffu, s, o);
        float inv = 1.0f / s;
#pragma unroll
        for (int q = 0; q < 4; q++)
            out[(b0 + r) * VOCAB + lane + q * 32] = v[q] * inv;
    }
}

// ===========================================================================
extern "C" void kernel_launch(void* const* d_in, const int* in_sizes, int n_in,
                              void* d_out, int out_size) {
    const int*   inputs = (const int*)d_in[0];
    const float* Wx     = (const float*)d_in[1];
    const float* Wh     = (const float*)d_in[2];
    const float* b      = (const float*)d_in[3];
    const float* Wd     = (const float*)d_in[4];
    const float* bd     = (const float*)d_in[5];
    float*       out    = (float*)d_out;

    cudaFuncSetAttribute(lstm_step_kernel,
                         cudaFuncAttributeMaxDynamicSharedMemorySize, SMEM_TOTAL);

    init_state_kernel<<<(BATCH * HID + 255) / 256, 256>>>();
    prep_wh_kernel<<<(256 * 1024) / 256, 256>>>(Wh);

    dim3 grid(BATCH / 128, 8);  // 64 x 8 = 512 CTAs
    for (int t = 0; t < SEQ; t++)
        lstm_step_kernel<<<grid, 256, SMEM_TOTAL>>>(t, inputs, Wx, b);

    dense_softmax_kernel<<<BATCH / DROWS, 128>>>(Wd, bd, out);
}